// round 6
// baseline (speedup 1.0000x reference)
#include <cuda_runtime.h>
#include <cuda_fp16.h>

#define TSTEPS 2048
#define HID    2048
#define INP    1024
#define NOUT   512
#define ZLEN   (HID + INP)
#define NCTA   148
#define JPER   14

#define SW_HALFS   (55 * 2048)
#define SHH_OFF    (SW_HALFS * 2)            /* 225280: h(t-1) half2, 4096 B */
#define SRED_OFF   (SHH_OFF + 4096)          /* 229376: partials [4][56] f32, 896 B */
#define SG_OFF     (SRED_OFF + 896)          /* 230272: G double buffer, 512 B */
#define SMEM_TOTAL (SG_OFF + 512)            /* 230784 */

__device__ float    d_G[(size_t)4 * HID * TSTEPS];   // [r][t], r = g*HID + j
__device__ unsigned d_bar;

__device__ __forceinline__ unsigned packh2(float a, float b) {
    __half2 h = __floats2half2_rn(a, b);
    return *(unsigned*)&h;
}
__device__ __forceinline__ unsigned long long packf2(float lo, float hi) {
    unsigned long long r;
    asm("mov.b64 %0, {%1, %2};" : "=l"(r) : "f"(lo), "f"(hi));
    return r;
}
__device__ __forceinline__ void unpackf2(unsigned long long v, float &lo, float &hi) {
    asm("mov.b64 {%0, %1}, %2;" : "=f"(lo), "=f"(hi) : "l"(v));
}
__device__ __forceinline__ unsigned long long addf32x2(unsigned long long a,
                                                       unsigned long long b) {
    unsigned long long r;
    asm("add.rn.f32x2 %0, %1, %2;" : "=l"(r) : "l"(a), "l"(b));
    return r;
}
__device__ __forceinline__ float sigmoidf_(float x) { return 1.0f / (1.0f + __expf(-x)); }
__device__ __forceinline__ float tanhf_(float x) {
    float e = __expf(2.0f * x); return 1.0f - 2.0f / (e + 1.0f);
}

// ---------------- GEMM for x-part preactivations (unchanged, proven) ----------
__global__ __launch_bounds__(256) void gemm_xpart(
    const float* __restrict__ Wf, const float* __restrict__ Wi,
    const float* __restrict__ Wc, const float* __restrict__ Wo,
    const float* __restrict__ bf, const float* __restrict__ bi,
    const float* __restrict__ bc, const float* __restrict__ bo,
    const float* __restrict__ X)
{
    __shared__ float As[16][132];
    __shared__ float Bs[16][132];
    const int bx = blockIdx.x, by = blockIdx.y;
    const int g = by >> 4, jb = (by & 15) << 7;
    const float* W  = (g == 0) ? Wf : (g == 1) ? Wi : (g == 2) ? Wc : Wo;
    const float* bb = (g == 0) ? bf : (g == 1) ? bi : (g == 2) ? bc : bo;
    const int tid = threadIdx.x, tx = tid & 15, ty = tid >> 4;
    float acc[8][8];
#pragma unroll
    for (int i = 0; i < 8; ++i)
#pragma unroll
        for (int j = 0; j < 8; ++j) acc[i][j] = 0.0f;
    for (int k0 = 0; k0 < INP; k0 += 16) {
#pragma unroll
        for (int i = 0; i < 2; ++i) {
            int f = tid + i * 256, row = f >> 2, kk = (f & 3) << 2;
            float4 v = *(const float4*)(W + (size_t)(jb + row) * ZLEN + HID + k0 + kk);
            As[kk][row] = v.x; As[kk+1][row] = v.y; As[kk+2][row] = v.z; As[kk+3][row] = v.w;
            float4 u = *(const float4*)(X + (size_t)((bx << 7) + row) * INP + k0 + kk);
            Bs[kk][row] = u.x; Bs[kk+1][row] = u.y; Bs[kk+2][row] = u.z; Bs[kk+3][row] = u.w;
        }
        __syncthreads();
#pragma unroll
        for (int k = 0; k < 16; ++k) {
            float a[8], b[8];
            *(float4*)&a[0] = *(const float4*)&As[k][ty*8];
            *(float4*)&a[4] = *(const float4*)&As[k][ty*8+4];
            *(float4*)&b[0] = *(const float4*)&Bs[k][tx*8];
            *(float4*)&b[4] = *(const float4*)&Bs[k][tx*8+4];
#pragma unroll
            for (int ii = 0; ii < 8; ++ii)
#pragma unroll
                for (int jj = 0; jj < 8; ++jj)
                    acc[ii][jj] = fmaf(a[ii], b[jj], acc[ii][jj]);
        }
        __syncthreads();
    }
#pragma unroll
    for (int ii = 0; ii < 8; ++ii) {
        const int r = (by << 7) + ty*8 + ii;
        const float bv = __ldg(bb + jb + ty*8 + ii);
        float4 s0 = {acc[ii][0]+bv, acc[ii][1]+bv, acc[ii][2]+bv, acc[ii][3]+bv};
        float4 s1 = {acc[ii][4]+bv, acc[ii][5]+bv, acc[ii][6]+bv, acc[ii][7]+bv};
        float* dst = d_G + (size_t)r * TSTEPS + (bx << 7) + tx*8;
        *(float4*)dst = s0; *(float4*)(dst + 4) = s1;
    }
}

// ---------------- persistent recurrent kernel --------------------------------
// Warps 0..27: gates; kg = wid&3 (k slice of 512), rg = wid>>2 (8 rows each).
//   Row index gr = rg*8 + r, gr = jj*4 + g. Rows 0..54 in SMEM, row 55 in regs.
// Warp 28: finalize + grid barrier.  Warps 29,30: y GEMV.  Warp 31: G prefetch.
// Warps 28..31 stage h(t-1) -> sHh (half2) at step start.
__global__ void __launch_bounds__(1024, 1) lstm_recurrent(
    const float* __restrict__ Wf, const float* __restrict__ Wi,
    const float* __restrict__ Wc, const float* __restrict__ Wo,
    const float* __restrict__ Wy, const float* __restrict__ by,
    float* __restrict__ out)
{
    extern __shared__ char smem[];
    __half*  sW   = (__half*)smem;
    __half*  sHh  = (__half*)(smem + SHH_OFF);
    float*   sRed = (float*)(smem + SRED_OFF);
    float*   sG   = (float*)(smem + SG_OFF);

    const int tid = threadIdx.x, wid = tid >> 5, lane = tid & 31;
    const int bid = blockIdx.x, jb = bid * JPER;
    int njj = HID - jb; njj = njj < 0 ? 0 : (njj > JPER ? JPER : njj);
    float* out_y = out;
    float* out_h = out + (size_t)TSTEPS * NOUT;
    unsigned* barp = &d_bar;

    // ---- fill weight SMEM: rows gr = 0..54, full k ----
    for (int c = tid; c < 55 * 256; c += 1024) {
        int gr = c >> 8;
        int k8 = (c & 255) << 3;
        int jj = gr >> 2, g = gr & 3;
        const float* W = (g == 0) ? Wf : (g == 1) ? Wi : (g == 2) ? Wc : Wo;
        uint4 u = {0u, 0u, 0u, 0u};
        if (jj < njj) {
            const float* p = W + (size_t)(jb + jj) * ZLEN + k8;
            float4 v0 = *(const float4*)p;
            float4 v1 = *(const float4*)(p + 4);
            u.x = packh2(v0.x, v0.y); u.y = packh2(v0.z, v0.w);
            u.z = packh2(v1.x, v1.y); u.w = packh2(v1.z, v1.w);
        }
        *(uint4*)(sW + gr * 2048 + k8) = u;
    }

    // ---- row 55 (jj=13, gate o) tail in registers of rg==6 gate warps ----
    unsigned wtail[8] = {0,0,0,0,0,0,0,0};
    const int kg = wid & 3, rg = wid >> 2;
    if (wid < 28 && rg == 6 && 13 < njj) {
        const float* p = Wo + (size_t)(jb + 13) * ZLEN;
#pragma unroll
        for (int it = 0; it < 2; ++it)
#pragma unroll
            for (int q = 0; q < 4; ++q) {
                int k = kg * 512 + it * 256 + lane * 8 + q * 2;
                wtail[it * 4 + q] = packh2(p[k], p[k + 1]);
            }
    }

    // preload G(0)
    if (wid == 31) {
        for (int i = lane; i < 56; i += 32) {
            int jj = i >> 2, g = i & 3;
            sG[i] = (jj < njj) ? __ldg(&d_G[((size_t)(g * HID + jb + jj)) * TSTEPS]) : 0.0f;
        }
    }

    float c_st = 0.0f;                      // finalize warp, lane = jj
    float by0 = 0.0f, by1 = 0.0f;
    int   r0 = 0;
    const bool doY = (bid < 128);
    if ((wid == 29 || wid == 30) && doY) {
        r0 = bid * 4 + (wid - 29) * 2;
        by0 = __ldg(by + r0); by1 = __ldg(by + r0 + 1);
    }
    __syncthreads();

    for (int t = 0; t <= TSTEPS; ++t) {
        if (t > 0 && wid == 28 && lane == 0) {
            const unsigned target = (unsigned)t * (unsigned)NCTA;
            unsigned v;
            do {
                asm volatile("ld.acquire.gpu.global.u32 %0, [%1];"
                             : "=r"(v) : "l"(barp) : "memory");
            } while (v < target);
        }
        __syncthreads();                                     // S1

        if (wid >= 28) {                                     // stage h(t-1) -> half2
            int i = tid - 896;                               // 0..127, 16 halfs each
            uint4 u0 = {0,0,0,0}, u1 = {0,0,0,0};
            if (t > 0) {
                const float* hp = out_h + (size_t)(t - 1) * HID + i * 16;
                float4 a = __ldcg((const float4*)hp);
                float4 b = __ldcg((const float4*)(hp + 4));
                float4 c = __ldcg((const float4*)(hp + 8));
                float4 d = __ldcg((const float4*)(hp + 12));
                u0.x = packh2(a.x, a.y); u0.y = packh2(a.z, a.w);
                u0.z = packh2(b.x, b.y); u0.w = packh2(b.z, b.w);
                u1.x = packh2(c.x, c.y); u1.y = packh2(c.z, c.w);
                u1.z = packh2(d.x, d.y); u1.w = packh2(d.z, d.w);
            }
            *(uint4*)(sHh + i * 16)     = u0;
            *(uint4*)(sHh + i * 16 + 8) = u1;
        }
        __syncthreads();                                     // S2

        if (wid < 28) {
            if (t < TSTEPS) {
                __half2 acc[8];
#pragma unroll
                for (int r = 0; r < 8; ++r) acc[r] = __floats2half2_rn(0.f, 0.f);
#pragma unroll
                for (int it = 0; it < 2; ++it) {
                    uint4 hv = *(const uint4*)(sHh + kg * 512 + it * 256 + lane * 8);
                    __half2 h0 = *(__half2*)&hv.x, h1 = *(__half2*)&hv.y;
                    __half2 h2 = *(__half2*)&hv.z, h3 = *(__half2*)&hv.w;
#pragma unroll
                    for (int r = 0; r < 8; ++r) {
                        uint4 wv;
                        if (r == 7 && rg == 6) {
                            wv.x = wtail[it*4]; wv.y = wtail[it*4+1];
                            wv.z = wtail[it*4+2]; wv.w = wtail[it*4+3];
                        } else {
                            wv = *(const uint4*)(sW + (rg * 8 + r) * 2048
                                                 + kg * 512 + it * 256 + lane * 8);
                        }
                        acc[r] = __hfma2(*(__half2*)&wv.x, h0, acc[r]);
                        acc[r] = __hfma2(*(__half2*)&wv.y, h1, acc[r]);
                        acc[r] = __hfma2(*(__half2*)&wv.z, h2, acc[r]);
                        acc[r] = __hfma2(*(__half2*)&wv.w, h3, acc[r]);
                    }
                }
                float s[8];
#pragma unroll
                for (int r = 0; r < 8; ++r) {
                    float2 f = __half22float2(acc[r]);
                    s[r] = f.x + f.y;
                }
                unsigned long long v0 = packf2(s[0], s[1]);
                unsigned long long v1 = packf2(s[2], s[3]);
                unsigned long long v2 = packf2(s[4], s[5]);
                unsigned long long v3 = packf2(s[6], s[7]);
#pragma unroll
                for (int off = 16; off > 0; off >>= 1) {
                    v0 = addf32x2(v0, __shfl_xor_sync(0xFFFFFFFFu, v0, off));
                    v1 = addf32x2(v1, __shfl_xor_sync(0xFFFFFFFFu, v1, off));
                    v2 = addf32x2(v2, __shfl_xor_sync(0xFFFFFFFFu, v2, off));
                    v3 = addf32x2(v3, __shfl_xor_sync(0xFFFFFFFFu, v3, off));
                }
                if (lane == 0) {
                    float lo, hi;
                    float* dst = sRed + kg * 56 + rg * 8;
                    unpackf2(v0, lo, hi); dst[0] = lo; dst[1] = hi;
                    unpackf2(v1, lo, hi); dst[2] = lo; dst[3] = hi;
                    unpackf2(v2, lo, hi); dst[4] = lo; dst[5] = hi;
                    unpackf2(v3, lo, hi); dst[6] = lo; dst[7] = hi;
                }
                asm volatile("bar.sync 1, 928;" ::: "memory");
            }
        } else if (wid == 28) {
            if (t < TSTEPS) {
                asm volatile("bar.sync 1, 928;" ::: "memory");
                if (lane < njj) {
                    float4 p0 = *(const float4*)(sRed + 0 * 56 + lane * 4);
                    float4 p1 = *(const float4*)(sRed + 1 * 56 + lane * 4);
                    float4 p2 = *(const float4*)(sRed + 2 * 56 + lane * 4);
                    float4 p3 = *(const float4*)(sRed + 3 * 56 + lane * 4);
                    float4 gv = *(const float4*)(sG + (t & 1) * 64 + lane * 4);
                    float pf = p0.x + p1.x + p2.x + p3.x + gv.x;
                    float pi = p0.y + p1.y + p2.y + p3.y + gv.y;
                    float pc = p0.z + p1.z + p2.z + p3.z + gv.z;
                    float po = p0.w + p1.w + p2.w + p3.w + gv.w;
                    float fg = sigmoidf_(pf);
                    float ig = sigmoidf_(pi);
                    float cc = tanhf_(pc);
                    float og = sigmoidf_(po);
                    c_st = fg * c_st + ig * cc;
                    out_h[(size_t)t * HID + jb + lane] = og * tanhf_(c_st);
                }
                if (lane == 0)
                    asm volatile("red.release.gpu.global.add.u32 [%0], %1;"
                                 :: "l"(barp), "r"(1u) : "memory");
            }
        } else if (wid == 29 || wid == 30) {
            if (t >= 1 && doY) {
                const float* wy0 = Wy + (size_t)r0 * HID;
                const float* wy1 = wy0 + HID;
                float s0 = 0.0f, s1 = 0.0f;
#pragma unroll
                for (int it = 0; it < 8; ++it) {
                    int k = it * 256 + lane * 8;
                    uint4 hv = *(const uint4*)(sHh + k);
                    float2 h0 = __half22float2(*(__half2*)&hv.x);
                    float2 h1 = __half22float2(*(__half2*)&hv.y);
                    float2 h2 = __half22float2(*(__half2*)&hv.z);
                    float2 h3 = __half22float2(*(__half2*)&hv.w);
                    float4 a0 = __ldg((const float4*)(wy0 + k));
                    float4 a1 = __ldg((const float4*)(wy0 + k + 4));
                    float4 b0 = __ldg((const float4*)(wy1 + k));
                    float4 b1 = __ldg((const float4*)(wy1 + k + 4));
                    s0 = fmaf(a0.x, h0.x, s0); s0 = fmaf(a0.y, h0.y, s0);
                    s0 = fmaf(a0.z, h1.x, s0); s0 = fmaf(a0.w, h1.y, s0);
                    s0 = fmaf(a1.x, h2.x, s0); s0 = fmaf(a1.y, h2.y, s0);
                    s0 = fmaf(a1.z, h3.x, s0); s0 = fmaf(a1.w, h3.y, s0);
                    s1 = fmaf(b0.x, h0.x, s1); s1 = fmaf(b0.y, h0.y, s1);
                    s1 = fmaf(b0.z, h1.x, s1); s1 = fmaf(b0.w, h1.y, s1);
                    s1 = fmaf(b1.x, h2.x, s1); s1 = fmaf(b1.y, h2.y, s1);
                    s1 = fmaf(b1.z, h3.x, s1); s1 = fmaf(b1.w, h3.y, s1);
                }
#pragma unroll
                for (int off = 16; off > 0; off >>= 1) {
                    s0 += __shfl_xor_sync(0xFFFFFFFFu, s0, off);
                    s1 += __shfl_xor_sync(0xFFFFFFFFu, s1, off);
                }
                if (lane == 0) {
                    out_y[(size_t)(t - 1) * NOUT + r0]     = s0 + by0;
                    out_y[(size_t)(t - 1) * NOUT + r0 + 1] = s1 + by1;
                }
            }
        } else {                                    // wid 31: prefetch G(t+1)
            if (t + 1 < TSTEPS) {
                for (int i = lane; i < 56; i += 32) {
                    int jj = i >> 2, g = i & 3;
                    sG[((t + 1) & 1) * 64 + i] = (jj < njj)
                        ? __ldg(&d_G[((size_t)(g * HID + jb + jj)) * TSTEPS + (t + 1)])
                        : 0.0f;
                }
            }
        }
    }
}

extern "C" void kernel_launch(void* const* d_in, const int* in_sizes, int n_in,
                              void* d_out, int out_size) {
    (void)in_sizes; (void)n_in; (void)out_size;
    const float* X  = (const float*)d_in[0];
    const float* Wf = (const float*)d_in[1];
    const float* bf = (const float*)d_in[2];
    const float* Wi = (const float*)d_in[3];
    const float* bi = (const float*)d_in[4];
    const float* Wc = (const float*)d_in[5];
    const float* bc = (const float*)d_in[6];
    const float* Wo = (const float*)d_in[7];
    const float* bo = (const float*)d_in[8];
    const float* Wy = (const float*)d_in[9];
    const float* by = (const float*)d_in[10];
    float* out = (float*)d_out;

    cudaFuncSetAttribute(lstm_recurrent,
                         cudaFuncAttributeMaxDynamicSharedMemorySize, SMEM_TOTAL);
    void* barp = nullptr;
    cudaGetSymbolAddress(&barp, d_bar);
    cudaMemsetAsync(barp, 0, sizeof(unsigned), 0);

    gemm_xpart<<<dim3(16, 64), 256>>>(Wf, Wi, Wc, Wo, bf, bi, bc, bo, X);
    lstm_recurrent<<<NCTA, 1024, SMEM_TOTAL>>>(Wf, Wi, Wc, Wo, Wy, by, out);
}